// round 1
// baseline (speedup 1.0000x reference)
#include <cuda_runtime.h>
#include <math.h>

// Problem constants (fixed by the dataset)
#define NN 50000
#define EE 800000
#define LAT 64
#define HID 128
#define GD 16

// Scratch (device globals: allocation-free rule)
__device__ float g_h[NN * LAT];      // node latent state
__device__ float g_e[EE * LAT];      // edge features (step t -> t+1)
__device__ float g_recv[NN * LAT];   // aggregated messages

typedef unsigned long long u64;

#define FMA2(d, a, b) asm("fma.rn.f32x2 %0, %1, %2, %0;" : "+l"(d) : "l"(a), "l"(b))

__device__ __forceinline__ float2 unpack2(u64 v) {
    float2 r;
    asm("mov.b64 {%0, %1}, %2;" : "=f"(r.x), "=f"(r.y) : "l"(v));
    return r;
}

// jax.nn.gelu (approximate=True): 0.5*x*(1+tanh(sqrt(2/pi)*(x+0.044715 x^3)))
// tanh via exp (2 MUFU) for ~1e-7 accuracy (tanh.approx would be ~1e-3 risky).
__device__ __forceinline__ float gelu_t(float x) {
    float y = 0.7978845608028654f * (x + 0.044715f * x * x * x);
    float e = __expf(2.0f * y);
    float th = 1.0f - __fdividef(2.0f, e + 1.0f);
    return 0.5f * x * (1.0f + th);
}

// ---------------------------------------------------------------------------
// embed: h = nodes @ embed_w + embed_b   (N x 7) @ (7 x 64)
// ---------------------------------------------------------------------------
__global__ void embed_kernel(const float* __restrict__ nodes,
                             const float* __restrict__ w,
                             const float* __restrict__ b, int Nv) {
    int idx = blockIdx.x * blockDim.x + threadIdx.x;
    if (idx >= Nv * LAT) return;
    int n = idx >> 6, j = idx & 63;
    float a = b[j];
#pragma unroll
    for (int k = 0; k < 7; k++) a += nodes[n * 7 + k] * w[k * LAT + j];
    g_h[idx] = a;
}

__global__ void zero_recv_kernel(int n) {
    int i = blockIdx.x * blockDim.x + threadIdx.x;
    if (i < n) g_recv[i] = 0.0f;
}

// ---------------------------------------------------------------------------
// Fused edge MLP:  e = gelu([e?,s,r,g] @ w1 + b1) @ w2 + b2
// then atomicAdd into recv[receiver], optionally write e.
// Warp processes ME=4 edges; weights transposed in smem for f32x2 inner loop.
// ---------------------------------------------------------------------------
template <int DIN, int DINP, bool HAS_E>
__global__ __launch_bounds__(256, 1) void edge_kernel(
    const int* __restrict__ senders, const int* __restrict__ receivers,
    const float* __restrict__ gvec,
    const float* __restrict__ w1, const float* __restrict__ b1,
    const float* __restrict__ w2, const float* __restrict__ b2,
    int En, int write_e) {
    constexpr int EW = 8, ME = 4, W2P = 130;
    extern __shared__ float sm[];
    float* w1t = sm;                       // 128 * DINP   [j][k] transposed
    float* b1s = w1t + 128 * DINP;         // 128
    float* w2t = b1s + 128;                // 64 * W2P     [j][k] transposed
    float* b2s = w2t + 64 * W2P;           // 64
    float* gs  = b2s + 64;                 // 16
    float* inb = gs + 16;                  // EW*ME*DINP
    float* hid = inb + EW * ME * DINP;     // EW*ME*128

    int tid = threadIdx.x;
    for (int i = tid; i < DIN * 128; i += 256) {
        int k = i / 128, j = i % 128;
        w1t[j * DINP + k] = w1[i];
    }
    for (int i = tid; i < 128; i += 256) b1s[i] = b1[i];
    for (int i = tid; i < 128 * 64; i += 256) {
        int k = i / 64, j = i % 64;
        w2t[j * W2P + k] = w2[i];
    }
    if (tid < 64) b2s[tid] = b2[tid];
    if (tid < GD) gs[tid] = gvec[tid];
    __syncthreads();

    int warp = tid >> 5, lane = tid & 31;
    float* myin = inb + warp * ME * DINP;
    float* myhid = hid + warp * ME * 128;
    int nTiles = (En + ME - 1) / ME;

    for (int tile = blockIdx.x * EW + warp; tile < nTiles; tile += gridDim.x * EW) {
        int ebase = tile * ME;
        int rcv[ME];
        // ---- gather inputs into smem (h is L2-resident) ----
#pragma unroll
        for (int m = 0; m < ME; m++) {
            int eid = ebase + m;
            if (eid >= En) eid = En - 1;
            int s = senders[eid];
            rcv[m] = receivers[eid];
            float* ib = myin + m * DINP;
            int off = 0;
            if (HAS_E) {
                ib[lane]      = g_e[eid * LAT + lane];
                ib[32 + lane] = g_e[eid * LAT + 32 + lane];
                off = 64;
            }
            ib[off + lane]      = g_h[s * LAT + lane];
            ib[off + 32 + lane] = g_h[s * LAT + 32 + lane];
            int r = rcv[m];
            ib[off + 64 + lane] = g_h[r * LAT + lane];
            ib[off + 96 + lane] = g_h[r * LAT + 32 + lane];
            if (lane < GD) ib[off + 128 + lane] = gs[lane];
        }
        __syncwarp();

        // ---- layer 1: hidden (lane covers j = lane + 32*jj) ----
        u64 acc[4][ME];
#pragma unroll
        for (int jj = 0; jj < 4; jj++)
#pragma unroll
            for (int m = 0; m < ME; m++) acc[jj][m] = 0ull;

#pragma unroll 2
        for (int k2 = 0; k2 < DIN / 2; k2++) {
            u64 bj[4];
#pragma unroll
            for (int jj = 0; jj < 4; jj++)
                bj[jj] = *(const u64*)(w1t + (lane + 32 * jj) * DINP + 2 * k2);
#pragma unroll
            for (int m = 0; m < ME; m++) {
                u64 a = *(const u64*)(myin + m * DINP + 2 * k2);
#pragma unroll
                for (int jj = 0; jj < 4; jj++) FMA2(acc[jj][m], a, bj[jj]);
            }
        }
#pragma unroll
        for (int m = 0; m < ME; m++)
#pragma unroll
            for (int jj = 0; jj < 4; jj++) {
                int j = lane + 32 * jj;
                float2 v = unpack2(acc[jj][m]);
                myhid[m * 128 + j] = gelu_t(v.x + v.y + b1s[j]);
            }
        __syncwarp();

        // ---- layer 2: out (lane covers j = lane, lane+32) ----
        u64 o[2][ME];
#pragma unroll
        for (int m = 0; m < ME; m++) { o[0][m] = 0ull; o[1][m] = 0ull; }
#pragma unroll 2
        for (int k2 = 0; k2 < 64; k2++) {
            u64 b0 = *(const u64*)(w2t + lane * W2P + 2 * k2);
            u64 b1v = *(const u64*)(w2t + (lane + 32) * W2P + 2 * k2);
#pragma unroll
            for (int m = 0; m < ME; m++) {
                u64 a = *(const u64*)(myhid + m * 128 + 2 * k2);
                FMA2(o[0][m], a, b0);
                FMA2(o[1][m], a, b1v);
            }
        }
#pragma unroll
        for (int m = 0; m < ME; m++) {
            int eid = ebase + m;
            if (eid >= En) continue;
            float2 v0 = unpack2(o[0][m]);
            float2 v1 = unpack2(o[1][m]);
            float u0 = v0.x + v0.y + b2s[lane];
            float u1 = v1.x + v1.y + b2s[lane + 32];
            if (write_e) {
                g_e[eid * LAT + lane] = u0;
                g_e[eid * LAT + 32 + lane] = u1;
            }
            atomicAdd(&g_recv[rcv[m] * LAT + lane], u0);
            atomicAdd(&g_recv[rcv[m] * LAT + 32 + lane], u1);
        }
        __syncwarp();
    }
}

// ---------------------------------------------------------------------------
// Fused node MLP + residual + LayerNorm (in place on g_h)
// ---------------------------------------------------------------------------
__global__ __launch_bounds__(256, 1) void node_kernel(
    const float* __restrict__ gvec,
    const float* __restrict__ w1, const float* __restrict__ b1,
    const float* __restrict__ w2, const float* __restrict__ b2,
    const float* __restrict__ lnsc, const float* __restrict__ lnbi, int Nv) {
    constexpr int DIN = 144, DINP = 146, EW = 8, ME = 4, W2P = 130;
    extern __shared__ float sm[];
    float* w1t = sm;
    float* b1s = w1t + 128 * DINP;
    float* w2t = b1s + 128;
    float* b2s = w2t + 64 * W2P;
    float* gs  = b2s + 64;
    float* lns = gs + GD;                  // 64
    float* lnb = lns + 64;                 // 64
    float* inb = lnb + 64;
    float* hid = inb + EW * ME * DINP;

    int tid = threadIdx.x;
    for (int i = tid; i < DIN * 128; i += 256) {
        int k = i / 128, j = i % 128;
        w1t[j * DINP + k] = w1[i];
    }
    for (int i = tid; i < 128; i += 256) b1s[i] = b1[i];
    for (int i = tid; i < 128 * 64; i += 256) {
        int k = i / 64, j = i % 64;
        w2t[j * W2P + k] = w2[i];
    }
    if (tid < 64) { b2s[tid] = b2[tid]; lns[tid] = lnsc[tid]; lnb[tid] = lnbi[tid]; }
    if (tid < GD) gs[tid] = gvec[tid];
    __syncthreads();

    int warp = tid >> 5, lane = tid & 31;
    float* myin = inb + warp * ME * DINP;
    float* myhid = hid + warp * ME * 128;
    int nTiles = (Nv + ME - 1) / ME;

    for (int tile = blockIdx.x * EW + warp; tile < nTiles; tile += gridDim.x * EW) {
        int nbase = tile * ME;
#pragma unroll
        for (int m = 0; m < ME; m++) {
            int nid = nbase + m;
            if (nid >= Nv) nid = Nv - 1;
            float* ib = myin + m * DINP;
            ib[lane]      = g_h[nid * LAT + lane];
            ib[32 + lane] = g_h[nid * LAT + 32 + lane];
            ib[64 + lane] = g_recv[nid * LAT + lane];
            ib[96 + lane] = g_recv[nid * LAT + 32 + lane];
            if (lane < GD) ib[128 + lane] = gs[lane];
        }
        __syncwarp();

        u64 acc[4][ME];
#pragma unroll
        for (int jj = 0; jj < 4; jj++)
#pragma unroll
            for (int m = 0; m < ME; m++) acc[jj][m] = 0ull;
#pragma unroll 2
        for (int k2 = 0; k2 < DIN / 2; k2++) {
            u64 bj[4];
#pragma unroll
            for (int jj = 0; jj < 4; jj++)
                bj[jj] = *(const u64*)(w1t + (lane + 32 * jj) * DINP + 2 * k2);
#pragma unroll
            for (int m = 0; m < ME; m++) {
                u64 a = *(const u64*)(myin + m * DINP + 2 * k2);
#pragma unroll
                for (int jj = 0; jj < 4; jj++) FMA2(acc[jj][m], a, bj[jj]);
            }
        }
#pragma unroll
        for (int m = 0; m < ME; m++)
#pragma unroll
            for (int jj = 0; jj < 4; jj++) {
                int j = lane + 32 * jj;
                float2 v = unpack2(acc[jj][m]);
                myhid[m * 128 + j] = gelu_t(v.x + v.y + b1s[j]);
            }
        __syncwarp();

        u64 o[2][ME];
#pragma unroll
        for (int m = 0; m < ME; m++) { o[0][m] = 0ull; o[1][m] = 0ull; }
#pragma unroll 2
        for (int k2 = 0; k2 < 64; k2++) {
            u64 b0 = *(const u64*)(w2t + lane * W2P + 2 * k2);
            u64 b1v = *(const u64*)(w2t + (lane + 32) * W2P + 2 * k2);
#pragma unroll
            for (int m = 0; m < ME; m++) {
                u64 a = *(const u64*)(myhid + m * 128 + 2 * k2);
                FMA2(o[0][m], a, b0);
                FMA2(o[1][m], a, b1v);
            }
        }
        // residual + LayerNorm, in place
#pragma unroll
        for (int m = 0; m < ME; m++) {
            int nid = nbase + m;
            float2 v0 = unpack2(o[0][m]);
            float2 v1 = unpack2(o[1][m]);
            float x0 = myin[m * DINP + lane]      + v0.x + v0.y + b2s[lane];
            float x1 = myin[m * DINP + 32 + lane] + v1.x + v1.y + b2s[lane + 32];
            float s = x0 + x1, q = x0 * x0 + x1 * x1;
#pragma unroll
            for (int d = 16; d; d >>= 1) {
                s += __shfl_xor_sync(0xffffffffu, s, d);
                q += __shfl_xor_sync(0xffffffffu, q, d);
            }
            float mu = s * (1.0f / 64.0f);
            float var = q * (1.0f / 64.0f) - mu * mu;
            float inv = rsqrtf(var + 1e-6f);
            if (nid < Nv) {
                g_h[nid * LAT + lane]      = (x0 - mu) * inv * lns[lane] + lnb[lane];
                g_h[nid * LAT + 32 + lane] = (x1 - mu) * inv * lns[32 + lane] + lnb[32 + lane];
            }
        }
        __syncwarp();
    }
}

// ---------------------------------------------------------------------------
// decode: out = h @ dec_w + dec_b   (warp per node)
// ---------------------------------------------------------------------------
__global__ void decode_kernel(const float* __restrict__ dec_w,
                              const float* __restrict__ dec_b,
                              float* __restrict__ out, int Nv) {
    int gwarp = (blockIdx.x * blockDim.x + threadIdx.x) >> 5;
    int lane = threadIdx.x & 31;
    int nWarps = (gridDim.x * blockDim.x) >> 5;
    for (int n = gwarp; n < Nv; n += nWarps) {
        float h0 = g_h[n * LAT + lane];
        float h1 = g_h[n * LAT + 32 + lane];
        float p[7];
#pragma unroll
        for (int k = 0; k < 7; k++)
            p[k] = h0 * dec_w[lane * 7 + k] + h1 * dec_w[(lane + 32) * 7 + k];
#pragma unroll
        for (int k = 0; k < 7; k++)
#pragma unroll
            for (int d = 16; d; d >>= 1) p[k] += __shfl_xor_sync(0xffffffffu, p[k], d);
        if (lane < 7) out[n * 7 + lane] = p[lane] + dec_b[lane];
    }
}

// ---------------------------------------------------------------------------
extern "C" void kernel_launch(void* const* d_in, const int* in_sizes, int n_in,
                              void* d_out, int out_size) {
    const float* nodes   = (const float*)d_in[0];
    const int*   senders = (const int*)d_in[1];
    const int*   recvrs  = (const int*)d_in[2];
    const float* g       = (const float*)d_in[3];
    const float* embed_w = (const float*)d_in[4];
    const float* embed_b = (const float*)d_in[5];
    const float* ew1f    = (const float*)d_in[6];
    const float* ew1r    = (const float*)d_in[7];
    const float* eb1     = (const float*)d_in[8];
    const float* ew2     = (const float*)d_in[9];
    const float* eb2     = (const float*)d_in[10];
    const float* nw1     = (const float*)d_in[11];
    const float* nb1     = (const float*)d_in[12];
    const float* nw2     = (const float*)d_in[13];
    const float* nb2     = (const float*)d_in[14];
    const float* lnsc    = (const float*)d_in[15];
    const float* lnbi    = (const float*)d_in[16];
    const float* dec_w   = (const float*)d_in[17];
    const float* dec_b   = (const float*)d_in[18];
    float* out = (float*)d_out;

    int En = in_sizes[1];
    int Nv = in_sizes[0] / 7;

    size_t sm_e0 = (size_t)(128 * 146 + 128 + 64 * 130 + 64 + 16 + 8 * 4 * 146 + 8 * 4 * 128) * 4;
    size_t sm_e1 = (size_t)(128 * 210 + 128 + 64 * 130 + 64 + 16 + 8 * 4 * 210 + 8 * 4 * 128) * 4;
    size_t sm_n  = (size_t)(128 * 146 + 128 + 64 * 130 + 64 + 16 + 128 + 8 * 4 * 146 + 8 * 4 * 128) * 4;

    cudaFuncSetAttribute(edge_kernel<144, 146, false>,
                         cudaFuncAttributeMaxDynamicSharedMemorySize, (int)sm_e0);
    cudaFuncSetAttribute(edge_kernel<208, 210, true>,
                         cudaFuncAttributeMaxDynamicSharedMemorySize, (int)sm_e1);
    cudaFuncSetAttribute(node_kernel,
                         cudaFuncAttributeMaxDynamicSharedMemorySize, (int)sm_n);

    const int GRID = 304;  // ~2 waves at 1 CTA/SM (large smem)

    embed_kernel<<<(Nv * LAT + 255) / 256, 256>>>(nodes, embed_w, embed_b, Nv);

    for (int t = 0; t < 3; t++) {
        zero_recv_kernel<<<(Nv * LAT + 255) / 256, 256>>>(Nv * LAT);
        if (t == 0) {
            edge_kernel<144, 146, false><<<GRID, 256, sm_e0>>>(
                senders, recvrs, g, ew1f, eb1, ew2, eb2, En, 1);
        } else {
            edge_kernel<208, 210, true><<<GRID, 256, sm_e1>>>(
                senders, recvrs, g,
                ew1r + (size_t)(t - 1) * 208 * 128,
                eb1 + t * 128, ew2 + (size_t)t * 128 * 64, eb2 + t * 64,
                En, (t == 2) ? 0 : 1);
        }
        node_kernel<<<GRID, 256, sm_n>>>(
            g, nw1 + (size_t)t * 144 * 128, nb1 + t * 128,
            nw2 + (size_t)t * 128 * 64, nb2 + t * 64,
            lnsc + t * 64, lnbi + t * 64, Nv);
    }

    decode_kernel<<<208, 256>>>(dec_w, dec_b, out, Nv);
}